// round 6
// baseline (speedup 1.0000x reference)
#include <cuda_runtime.h>
#include <cuda_bf16.h>

// Problem constants
#define BSZ   1024
#define TLEN  512
#define NX    32
#define NU    8
#define HN    64
#define G4    256        // 4*H
#define HB    8          // batch rows per recurrent CTA
#define NCTA  (BSZ / HB) // 128 recurrent CTAs
#define RTHR  256        // threads per recurrent CTA: 8 warps = 2/SMSP

// 512 MB scratch for hoisted layer-0 input projection, layout [T][B][4H]
__device__ float g_xproj[(size_t)TLEN * BSZ * G4];

typedef unsigned long long ull;

// ---------------------------------------------------------------------------
// helpers: packed f32x2 math (Blackwell-only FFMA2 via PTX)
// ---------------------------------------------------------------------------
__device__ __forceinline__ ull pack2(float lo, float hi) {
    ull r;
    asm("mov.b64 %0, {%1, %2};" : "=l"(r) : "f"(lo), "f"(hi));
    return r;
}
__device__ __forceinline__ ull pack_dup(float v) {
    ull r;
    asm("mov.b64 %0, {%1, %1};" : "=l"(r) : "f"(v));
    return r;
}
__device__ __forceinline__ void fma2(ull& d, ull a, ull b) {
    asm("fma.rn.f32x2 %0, %1, %2, %0;" : "+l"(d) : "l"(a), "l"(b));
}
__device__ __forceinline__ float2 unpack2(ull v) {
    float2 f;
    asm("mov.b64 {%0, %1}, %2;" : "=f"(f.x), "=f"(f.y) : "l"(v));
    return f;
}
__device__ __forceinline__ float getc(const float4& v, int i) {
    return (i == 0) ? v.x : (i == 1) ? v.y : (i == 2) ? v.z : v.w;
}

__device__ __forceinline__ float sig_f(float x) {
    return __fdividef(1.0f, 1.0f + __expf(-x));
}
__device__ __forceinline__ float tanh_f(float x) {
    return 1.0f - __fdividef(2.0f, __expf(2.0f * x) + 1.0f);
}

// ---------------------------------------------------------------------------
// Kernel 1: layer-0 input projection GEMM
// xproj[t][b][g] = sum_d seq[b][t][d] * W_ih0[g][d] + b_ih0[g] + b_hh0[g]
// CTA: 256 threads, 64 batch rows at fixed t. grid = T * (B/64) = 8192
// f32x2: even-d lo lane / odd-d hi lane; operands adjacent in memory ->
// direct 64-bit loads, zero pack instructions; one horizontal add per output.
// ---------------------------------------------------------------------------
__global__ void __launch_bounds__(256) xproj_kernel(
    const float* __restrict__ x, const float* __restrict__ u,
    const float* __restrict__ Wih0, const float* __restrict__ bih0,
    const float* __restrict__ bhh0)
{
    const int cta = blockIdx.x;
    const int t  = cta >> 4;
    const int b0 = (cta & 15) << 6;

    __shared__ float sseq[64][40];
    const int tid = threadIdx.x;

    for (int idx = tid; idx < 64 * 32; idx += 256) {
        int r = idx >> 5, i = idx & 31;
        sseq[r][i] = x[(size_t)(b0 + r) * (TLEN * NX) + t * NX + i];
    }
    for (int idx = tid; idx < 64 * 8; idx += 256) {
        int r = idx >> 3, i = idx & 7;
        sseq[r][32 + i] = u[(size_t)(b0 + r) * (TLEN * NU) + t * NU + i];
    }

    const int j = tid;
    const ull* wrow = (const ull*)(Wih0 + (size_t)j * 40);
    ull wd[20];
#pragma unroll
    for (int q = 0; q < 20; q++) wd[q] = wrow[q];
    const float bias = __ldg(&bih0[j]) + __ldg(&bhh0[j]);

    __syncthreads();

    float* outp = &g_xproj[(size_t)t * (BSZ * G4) + (size_t)b0 * G4 + j];
#pragma unroll 2
    for (int r = 0; r < 64; r++) {
        const ulonglong2* s2 = (const ulonglong2*)sseq[r];
        ull acc = pack2(bias, 0.0f);
#pragma unroll
        for (int q = 0; q < 10; q++) {
            ulonglong2 v = s2[q];
            fma2(acc, v.x, wd[2 * q + 0]);
            fma2(acc, v.y, wd[2 * q + 1]);
        }
        float2 f = unpack2(acc);
        outp[(size_t)r * G4] = f.x + f.y;
    }
}

// ---------------------------------------------------------------------------
// Recurrent matvec, half-warp batch split. Thread handles rows (j0, j1) and
// the 4 batches of its half. hsrc is pre-offset by half*4 floats.
// acc[0..1] = row j0 (batch pairs 0,1), acc[2..3] = row j1.
// Per k: one 16B h load per half (32B/warp = 1 crossbar phase).
// ---------------------------------------------------------------------------
__device__ __forceinline__ void mv16(const float4* __restrict__ wpan,
                                     const float* __restrict__ hsrc,
                                     int j0, int j1, ull acc[4])
{
#pragma unroll 4
    for (int kk = 0; kk < 16; kk++) {
        float4 w0 = wpan[kk * 256 + j0];
        float4 w1 = wpan[kk * 256 + j1];
#pragma unroll
        for (int k = 0; k < 4; k++) {
            ulonglong2 h2 = *(const ulonglong2*)(hsrc + (kk * 4 + k) * 8);
            ull w0d = pack_dup(getc(w0, k));
            ull w1d = pack_dup(getc(w1, k));
            fma2(acc[0], h2.x, w0d);
            fma2(acc[1], h2.y, w0d);
            fma2(acc[2], h2.x, w1d);
            fma2(acc[3], h2.y, w1d);
        }
    }
}

// Fused: accA += h @ WA (rows j0,j1), accC += h @ WC, sharing h loads.
__device__ __forceinline__ void mv16_fused(const float4* __restrict__ wpA,
                                           const float4* __restrict__ wpC,
                                           const float* __restrict__ hsrc,
                                           int j0, int j1,
                                           ull accA[4], ull accC[4])
{
#pragma unroll 4
    for (int kk = 0; kk < 16; kk++) {
        float4 a0 = wpA[kk * 256 + j0];
        float4 a1 = wpA[kk * 256 + j1];
        float4 c0 = wpC[kk * 256 + j0];
        float4 c1 = wpC[kk * 256 + j1];
#pragma unroll
        for (int k = 0; k < 4; k++) {
            ulonglong2 h2 = *(const ulonglong2*)(hsrc + (kk * 4 + k) * 8);
            ull a0d = pack_dup(getc(a0, k));
            ull a1d = pack_dup(getc(a1, k));
            ull c0d = pack_dup(getc(c0, k));
            ull c1d = pack_dup(getc(c1, k));
            fma2(accA[0], h2.x, a0d);
            fma2(accA[1], h2.y, a0d);
            fma2(accA[2], h2.x, a1d);
            fma2(accA[3], h2.y, a1d);
            fma2(accC[0], h2.x, c0d);
            fma2(accC[1], h2.y, c0d);
            fma2(accC[2], h2.x, c1d);
            fma2(accC[3], h2.y, c1d);
        }
    }
}

// activations: row j0 always sigmoid (j0 in [0,128) = i,f); row j1 tanh if
// j1<192 (gate g) else sigmoid (gate o). Branch is warp-uniform.
// Stores thread's half: float4 at gact[j][half*4].
__device__ __forceinline__ void activate2(const ull acc[4], int j0, int j1,
                                          int half, float* __restrict__ gact)
{
    float2 q0 = unpack2(acc[0]), q1 = unpack2(acc[1]);
    float2 r0 = unpack2(acc[2]), r1 = unpack2(acc[3]);
    float a[4] = {q0.x, q0.y, q1.x, q1.y};
    float b[4] = {r0.x, r0.y, r1.x, r1.y};
#pragma unroll
    for (int q = 0; q < 4; q++) a[q] = sig_f(a[q]);
    if (j1 < 192) {
#pragma unroll
        for (int q = 0; q < 4; q++) b[q] = tanh_f(b[q]);
    } else {
#pragma unroll
        for (int q = 0; q < 4; q++) b[q] = sig_f(b[q]);
    }
    *(float4*)(gact + j0 * 8 + half * 4) = make_float4(a[0], a[1], a[2], a[3]);
    *(float4*)(gact + j1 * 8 + half * 4) = make_float4(b[0], b[1], b[2], b[3]);
}

// ---------------------------------------------------------------------------
// Kernel 2: persistent 2-layer LSTM recurrence + final FC
// grid = 128 CTAs x 256 threads (8 warps = 2/SMSP); CTA r owns batches [8r,8r+8)
// warp w, lane l: s=l&15, half=l>>4; rows j0=w*16+s, j1=j0+128; batches 4*half..+3
// Pipelined schedule (accA(t) produced in previous iteration's seg3):
//   seg1: prefetch xp(t+1); accC = b1 + h2(t-1)@Whh1 (mv16); act0(accA)->gact
//   sync
//   seg2: c1/h1(t) update -> hbf1
//   sync
//   seg3: fused: accC += h1(t)@Wih1  AND  accA' = xp(t+1) + h1(t)@Whh0
//         act1(accC)->gact
//   sync
//   seg4: c2/h2(t) update -> hbf2
//   sync
// ---------------------------------------------------------------------------
extern __shared__ float smem_dyn[];

__global__ void __launch_bounds__(RTHR, 1) lstm_recur_kernel(
    const float* __restrict__ Whh0,
    const float* __restrict__ Wih1, const float* __restrict__ Whh1,
    const float* __restrict__ bih1, const float* __restrict__ bhh1,
    const float* __restrict__ Wfc,  const float* __restrict__ bfc,
    float* __restrict__ out)
{
    // dynamic smem layout (floats):
    float* wp0  = smem_dyn;                 // 16*256*4 = 16384 (Whh0 panels)
    float* wp1  = wp0 + 16384;              // 32*256*4 = 32768 (Wih1 | Whh1)
    float* hbf  = wp1 + 32768;              // 128*8    = 1024 (h1 | h2)
    float* gact = hbf + 1024;               // 256*8    = 2048
    float* b1s  = gact + 2048;              // 256
    // total 52480 floats = 209920 B

    const int tid  = threadIdx.x;
    const int w    = tid >> 5;
    const int l    = tid & 31;
    const int s    = l & 15;
    const int half = l >> 4;
    const int j0   = w * 16 + s;      // row in [0,128): i,f gates
    const int j1   = j0 + 128;        // row in [128,256): g,o gates
    const int b0   = blockIdx.x * HB;

    // ---- stage weights into k-panel layout: wp[kk][j][k&3] = W[j][k] ----
    for (int idx = tid; idx < 256 * 64; idx += RTHR) {
        int jj = idx >> 6, k = idx & 63;
        wp0[((k >> 2) * 256 + jj) * 4 + (k & 3)] = Whh0[idx];
        wp1[((k >> 2) * 256 + jj) * 4 + (k & 3)] = Wih1[idx];
        int k2 = k + 64;
        wp1[((k2 >> 2) * 256 + jj) * 4 + (k2 & 3)] = Whh1[idx];
    }
    b1s[tid] = bih1[tid] + bhh1[tid];
    for (int idx = tid; idx < 1024; idx += RTHR) hbf[idx] = 0.0f;
    __syncthreads();

    const float4* wp0f4 = (const float4*)wp0;
    const float4* wp1f4 = (const float4*)wp1;   // chunks 0..15: Wih1, 16..31: Whh1
    float* hbf1 = hbf;                // h1, [k][8 batches]
    float* hbf2 = hbf + 512;          // h2
    const float* h1src = hbf1 + half * 4;   // pre-offset for this thread's half
    const float* h2src = hbf2 + half * 4;

    // cell state: thread owns unit mu = tid>>2, batch pair pb = tid&3
    // flat pair base p = 2*tid (covers all 256 unit/pair slots per layer)
    const int p = 2 * tid;
    float2 c1 = {0.f, 0.f}, c2 = {0.f, 0.f};

    // prologue: accA(0) = xproj(t=0) for this thread's rows/batches (h1(-1)=0)
    ull accA[4];
    {
        const float* xq = &g_xproj[(size_t)(b0 + 4 * half) * G4];
        accA[0] = pack2(__ldg(xq + 0 * G4 + j0), __ldg(xq + 1 * G4 + j0));
        accA[1] = pack2(__ldg(xq + 2 * G4 + j0), __ldg(xq + 3 * G4 + j0));
        accA[2] = pack2(__ldg(xq + 0 * G4 + j1), __ldg(xq + 1 * G4 + j1));
        accA[3] = pack2(__ldg(xq + 2 * G4 + j1), __ldg(xq + 3 * G4 + j1));
    }

#pragma unroll 1
    for (int t = 0; t < TLEN; t++) {
        // ---- seg1 ----
        int tn = t + 1; if (tn == TLEN) tn = 0;
        float xpn0[4], xpn1[4];
        {
            const float* xq =
                &g_xproj[(size_t)tn * (BSZ * G4) + (size_t)(b0 + 4 * half) * G4];
#pragma unroll
            for (int q = 0; q < 4; q++) {
                xpn0[q] = __ldg(xq + (size_t)q * G4 + j0);
                xpn1[q] = __ldg(xq + (size_t)q * G4 + j1);
            }
        }
        ull accC[4];
        {
            ull u0 = pack_dup(b1s[j0]);
            ull u1 = pack_dup(b1s[j1]);
            accC[0] = u0; accC[1] = u0; accC[2] = u1; accC[3] = u1;
        }
        mv16(wp1f4 + 16 * 256, h2src, j0, j1, accC);       // C2: h2(t-1)@Whh1
        activate2(accA, j0, j1, half, gact);               // act0 (overlap C2)
        __syncthreads();

        // ---- seg2: c1/h1 update ----
        {
            float2 gi = *(const float2*)(gact + p);
            float2 gf = *(const float2*)(gact + 512 + p);
            float2 gg = *(const float2*)(gact + 1024 + p);
            float2 go = *(const float2*)(gact + 1536 + p);
            c1.x = gf.x * c1.x + gi.x * gg.x;
            c1.y = gf.y * c1.y + gi.y * gg.y;
            float2 h; h.x = go.x * tanh_f(c1.x); h.y = go.y * tanh_f(c1.y);
            *(float2*)(hbf1 + p) = h;
        }
        __syncthreads();

        // ---- seg3: fused C1 (accC += h1@Wih1) and A(t+1) (= xp + h1@Whh0) ----
        accA[0] = pack2(xpn0[0], xpn0[1]);
        accA[1] = pack2(xpn0[2], xpn0[3]);
        accA[2] = pack2(xpn1[0], xpn1[1]);
        accA[3] = pack2(xpn1[2], xpn1[3]);
        mv16_fused(wp0f4, wp1f4, h1src, j0, j1, accA, accC);
        activate2(accC, j0, j1, half, gact);               // act1 (overlap)
        __syncthreads();

        // ---- seg4: c2/h2 update ----
        {
            float2 gi = *(const float2*)(gact + p);
            float2 gf = *(const float2*)(gact + 512 + p);
            float2 gg = *(const float2*)(gact + 1024 + p);
            float2 go = *(const float2*)(gact + 1536 + p);
            c2.x = gf.x * c2.x + gi.x * gg.x;
            c2.y = gf.y * c2.y + gi.y * gg.y;
            float2 h; h.x = go.x * tanh_f(c2.x); h.y = go.y * tanh_f(c2.y);
            *(float2*)(hbf2 + p) = h;
        }
        __syncthreads();
    }

    // ---- final FC: out[b][n] = b_fc[n] + sum_k h2[b][k] * W_fc[n][k] ----
    {
        const int b = tid >> 5, n = tid & 31;
        float acc = __ldg(&bfc[n]);
#pragma unroll
        for (int k = 0; k < HN; k++)
            acc = fmaf(hbf2[k * 8 + b], __ldg(&Wfc[n * HN + k]), acc);
        out[(b0 + b) * NX + n] = acc;
    }
}

// ---------------------------------------------------------------------------
extern "C" void kernel_launch(void* const* d_in, const int* in_sizes, int n_in,
                              void* d_out, int out_size)
{
    const float* x_seq = (const float*)d_in[0];
    const float* u_seq = (const float*)d_in[1];
    const float* Wih0  = (const float*)d_in[2];
    const float* Whh0  = (const float*)d_in[3];
    const float* bih0  = (const float*)d_in[4];
    const float* bhh0  = (const float*)d_in[5];
    const float* Wih1  = (const float*)d_in[6];
    const float* Whh1  = (const float*)d_in[7];
    const float* bih1  = (const float*)d_in[8];
    const float* bhh1  = (const float*)d_in[9];
    const float* Wfc   = (const float*)d_in[10];
    const float* bfc   = (const float*)d_in[11];
    float* out = (float*)d_out;

    const int SMEM_BYTES = 52480 * 4;  // 209920
    cudaFuncSetAttribute(lstm_recur_kernel,
                         cudaFuncAttributeMaxDynamicSharedMemorySize, SMEM_BYTES);

    xproj_kernel<<<TLEN * (BSZ / 64), 256>>>(x_seq, u_seq, Wih0, bih0, bhh0);
    lstm_recur_kernel<<<NCTA, RTHR, SMEM_BYTES>>>(Whh0, Wih1, Whh1, bih1, bhh1,
                                                  Wfc, bfc, out);
}